// round 4
// baseline (speedup 1.0000x reference)
#include <cuda_runtime.h>

// ---------------- problem constants ----------------
#define Gn   128
#define NPG  256
#define EPG  4096
#define Nn   (Gn*NPG)          // 32768 nodes
#define En   (Gn*EPG)          // 524288 edges
#define Kk   2048              // kept edges per group
#define GKn  (Gn*Kk)           // 262144

// output layout (all f32, flattened tuple in reference order)
#define OFF_SCORE 0
#define OFF_CW    (En)
#define OFF_DW    (En + GKn)
#define OFF_CEI   (En + 2*GKn)
#define OFF_FEI   (En + 4*GKn)
#define OFF_CMASK (En + 6*GKn)
#define OFF_FMASK (En + 6*GKn + Nn)

// ---------------- device scratch ----------------
__device__ float g_A[Nn*64];
__device__ float g_B[Nn*64];
__device__ float g_C[Nn*64];
__device__ float g_H1[Nn*64];
__device__ float g_H2[Nn*64];
__device__ float g_PA[Nn*256];
__device__ float g_PB[Nn*256];
__device__ int   g_rows[En];      // LOCAL src node id (0..255)
__device__ float g_ews[En];
__device__ int   g_start[Nn];
__device__ int   g_keepnodes[2*GKn];
__device__ int   g_dropnodes[2*GKn];
__device__ int   g_presC[Nn];
__device__ int   g_presD[Nn];
__device__ int   g_nidC[Nn];
__device__ int   g_nidD[Nn];
__device__ int   g_bsC[32];
__device__ int   g_bsD[32];

// ---------------- helpers ----------------
__device__ __forceinline__ int warp_incl_scan(int v) {
    int lane = threadIdx.x & 31;
#pragma unroll
    for (int o = 1; o < 32; o <<= 1) {
        int t = __shfl_up_sync(0xffffffffu, v, o);
        if (lane >= o) v += t;
    }
    return v;
}

__device__ __forceinline__ unsigned long long pk2(float x, float y) {
    unsigned long long r;
    asm("mov.b64 %0, {%1,%2};" : "=l"(r) : "f"(x), "f"(y));
    return r;
}
__device__ __forceinline__ void fma2(unsigned long long& d, unsigned long long a, unsigned long long b) {
    asm("fma.rn.f32x2 %0, %1, %2, %0;" : "+l"(d) : "l"(a), "l"(b));
}
__device__ __forceinline__ float2 up2(unsigned long long v) {
    float2 f;
    asm("mov.b64 {%0,%1}, %2;" : "=f"(f.x), "=f"(f.y) : "l"(v));
    return f;
}

// ---------------- deterministic per-group CSR (counting sort by dst) + zero pres ----------------
__global__ void __launch_bounds__(256) csr_build_k(const int* __restrict__ ei,
                                                   const float* __restrict__ ea) {
    __shared__ int hist[8][256];
    __shared__ int wsums[8];
    int g = blockIdx.x, tid = threadIdx.x;
    int w = tid >> 5, lane = tid & 31;
    int base = g * EPG;

    // fused zeroing of present arrays (one element per thread per array)
    g_presC[g * NPG + tid] = 0;
    g_presD[g * NPG + tid] = 0;

#pragma unroll
    for (int i = 0; i < 8; i++) hist[i][tid] = 0;
    __syncthreads();

    for (int rnd = 0; rnd < 16; rnd++) {
        int j = w * 512 + rnd * 32 + lane;
        int c = ei[En + base + j] - g * NPG;
        atomicAdd(&hist[w][c], 1);
    }
    __syncthreads();

    int s = 0;
#pragma unroll
    for (int i = 0; i < 8; i++) { int h = hist[i][tid]; hist[i][tid] = s; s += h; }
    int incl = warp_incl_scan(s);
    if (lane == 31) wsums[w] = incl;
    __syncthreads();
    if (tid == 0) { int a = 0; for (int i = 0; i < 8; i++) { int t = wsums[i]; wsums[i] = a; a += t; } }
    __syncthreads();
    int excl_c = incl - s + wsums[w];
    g_start[g * NPG + tid] = base + excl_c;
#pragma unroll
    for (int i = 0; i < 8; i++) hist[i][tid] += excl_c;
    __syncthreads();

    for (int rnd = 0; rnd < 16; rnd++) {
        int j = w * 512 + rnd * 32 + lane;
        int r = ei[base + j] - g * NPG;          // store LOCAL id
        int c = ei[En + base + j] - g * NPG;
        float wv = ea[base + j];
        unsigned mask = __match_any_sync(0xffffffffu, c);
        int rank = __popc(mask & ((1u << lane) - 1u));
        int cur = hist[w][c];
        __syncwarp();
        if (lane == (__ffs(mask) - 1)) hist[w][c] = cur + __popc(mask);
        g_rows[base + cur + rank] = r;
        g_ews[base + cur + rank]  = wv;
        __syncwarp();
    }
}

// ---------------- fused per-layer triple GEMM: A=X@W1'+b1, B=X@W2', C=X@W3'+b3 ----------
__global__ void __launch_bounds__(256, 2) gemm3_k(const float* __restrict__ X,
                                                  const float* __restrict__ W1,
                                                  const float* __restrict__ b1,
                                                  const float* __restrict__ W2,
                                                  const float* __restrict__ W3,
                                                  const float* __restrict__ b3) {
    extern __shared__ float sm3[];
    float* Xt  = sm3;             // [k][v] 64x64
    float* Ws0 = sm3 + 4096;      // [k][f]
    float* Ws1 = sm3 + 8192;
    float* Ws2 = sm3 + 12288;
    int tid = threadIdx.x;
    int vtile = blockIdx.x * 64;

    for (int t = tid; t < 4096; t += 256) {
        int i = t >> 6, k = t & 63;
        Xt[k * 64 + i]  = X[(vtile + i) * 64 + k];
        Ws0[k * 64 + i] = W1[i * 64 + k];
        Ws1[k * 64 + i] = W2[i * 64 + k];
        Ws2[k * 64 + i] = W3[i * 64 + k];
    }
    __syncthreads();

    int tv = tid >> 4, tf = tid & 15;
    int v0 = tv * 4, f0 = tf * 4;
    unsigned long long a0[4][2], a1[4][2], a2[4][2];
#pragma unroll
    for (int v = 0; v < 4; v++) {
        a0[v][0] = a0[v][1] = 0ull;
        a1[v][0] = a1[v][1] = 0ull;
        a2[v][0] = a2[v][1] = 0ull;
    }

#pragma unroll 4
    for (int k = 0; k < 64; k++) {
        float4 xa = *(const float4*)&Xt[k * 64 + v0];
        float4 w0 = *(const float4*)&Ws0[k * 64 + f0];
        float4 w1 = *(const float4*)&Ws1[k * 64 + f0];
        float4 w2 = *(const float4*)&Ws2[k * 64 + f0];
        unsigned long long p00 = pk2(w0.x, w0.y), p01 = pk2(w0.z, w0.w);
        unsigned long long p10 = pk2(w1.x, w1.y), p11 = pk2(w1.z, w1.w);
        unsigned long long p20 = pk2(w2.x, w2.y), p21 = pk2(w2.z, w2.w);
        float xs[4] = {xa.x, xa.y, xa.z, xa.w};
#pragma unroll
        for (int v = 0; v < 4; v++) {
            unsigned long long xd = pk2(xs[v], xs[v]);
            fma2(a0[v][0], xd, p00); fma2(a0[v][1], xd, p01);
            fma2(a1[v][0], xd, p10); fma2(a1[v][1], xd, p11);
            fma2(a2[v][0], xd, p20); fma2(a2[v][1], xd, p21);
        }
    }

    float4 bA = *(const float4*)&b1[f0];
    float4 bC = *(const float4*)&b3[f0];
#pragma unroll
    for (int v = 0; v < 4; v++) {
        int row = (vtile + v0 + v) * 64 + f0;
        float2 r0 = up2(a0[v][0]), r1 = up2(a0[v][1]);
        *(float4*)&g_A[row] = make_float4(r0.x + bA.x, r0.y + bA.y, r1.x + bA.z, r1.y + bA.w);
        r0 = up2(a1[v][0]); r1 = up2(a1[v][1]);
        *(float4*)&g_B[row] = make_float4(r0.x, r0.y, r1.x, r1.y);
        r0 = up2(a2[v][0]); r1 = up2(a2[v][1]);
        *(float4*)&g_C[row] = make_float4(r0.x + bC.x, r0.y + bC.y, r1.x + bC.z, r1.y + bC.w);
    }
}

// ---------------- per-group smem-staged gather-aggregate + combine ----------------
__global__ void __launch_bounds__(256) aggc2_k(const float* __restrict__ A,
                                               const float* __restrict__ B,
                                               const float* __restrict__ C,
                                               float* __restrict__ H, int doRelu) {
    extern __shared__ float As[];   // 256 x 64 = 64KB, [v][f]
    int g = blockIdx.x;
    const float4* Ag = (const float4*)(A + g * NPG * 64);
    for (int t = threadIdx.x; t < NPG * 16; t += 256)
        ((float4*)As)[t] = Ag[t];
    __syncthreads();

    int w = threadIdx.x >> 5, lane = threadIdx.x & 31;
#pragma unroll 1
    for (int d = 0; d < 32; d++) {
        int v = w * 32 + d;          // local dst
        int gv = g * NPG + v;
        int s = g_start[gv];
        int e = (v == NPG - 1) ? (g * EPG + EPG) : g_start[gv + 1];
        float2 acc = make_float2(0.f, 0.f);
        float ws = 0.f;
        for (int i = s; i < e; i++) {
            int r = g_rows[i];
            float wv = g_ews[i];
            float2 a = *(const float2*)&As[r * 64 + lane * 2];
            acc.x += wv * a.x;
            acc.y += wv * a.y;
            ws += wv;
        }
        float2 bv = *(const float2*)&B[gv * 64 + lane * 2];
        float2 cv = *(const float2*)&C[gv * 64 + lane * 2];
        float hx = acc.x - ws * bv.x + cv.x;
        float hy = acc.y - ws * bv.y + cv.y;
        if (doRelu) { hx = fmaxf(hx, 0.f); hy = fmaxf(hy, 0.f); }
        *(float2*)&H[gv * 64 + lane * 2] = make_float2(hx, hy);
    }
}

// ---------------- MLP projection GEMM: PA/PB in one launch, grid (512, 8) ----------
__global__ void __launch_bounds__(128) gemmP_k(const float* __restrict__ X,
                                               const float* __restrict__ Wm1,
                                               const float* __restrict__ bm1) {
    __shared__ __align__(16) float Xt[64 * 64];   // [k][v]
    __shared__ __align__(16) float Ws[64 * 64];   // [k][f]
    int tid = threadIdx.x;
    int vtile = blockIdx.x * 64;
    int y = blockIdx.y;
    int isB = (y >= 4);
    int ftile = (y & 3) * 64;
    const float* Wbase = Wm1 + (isB ? 64 : 0);
    float* Y = isB ? g_PB : g_PA;

#pragma unroll
    for (int t = tid; t < 4096; t += 128) {
        int i = t >> 6, k = t & 63;
        Xt[k * 64 + i] = X[(vtile + i) * 64 + k];
        Ws[k * 64 + i] = Wbase[(ftile + i) * 128 + k];
    }
    __syncthreads();

    int tv = tid >> 4, tf = tid & 15;
    int v0 = tv * 8, f0 = tf * 4;
    unsigned long long acc[8][2];
#pragma unroll
    for (int v = 0; v < 8; v++) { acc[v][0] = 0ull; acc[v][1] = 0ull; }

#pragma unroll 8
    for (int k = 0; k < 64; k++) {
        float4 xa = *(const float4*)&Xt[k * 64 + v0];
        float4 xb = *(const float4*)&Xt[k * 64 + v0 + 4];
        float4 wf = *(const float4*)&Ws[k * 64 + f0];
        unsigned long long w0 = pk2(wf.x, wf.y);
        unsigned long long w1 = pk2(wf.z, wf.w);
        float xs[8] = {xa.x, xa.y, xa.z, xa.w, xb.x, xb.y, xb.z, xb.w};
#pragma unroll
        for (int v = 0; v < 8; v++) {
            unsigned long long xd = pk2(xs[v], xs[v]);
            fma2(acc[v][0], xd, w0);
            fma2(acc[v][1], xd, w1);
        }
    }

    float4 bv = make_float4(0.f, 0.f, 0.f, 0.f);
    if (!isB) bv = *(const float4*)&bm1[ftile + f0];
#pragma unroll
    for (int v = 0; v < 8; v++) {
        float2 r0 = up2(acc[v][0]);
        float2 r1 = up2(acc[v][1]);
        *(float4*)&Y[(vtile + v0 + v) * 256 + ftile + f0] =
            make_float4(r0.x + bv.x, r0.y + bv.y, r1.x + bv.z, r1.y + bv.w);
    }
}

// ---------------- per-edge score: smem-staged relu-dot, kk-outer ----------------
#define ESTRIDE 68
__global__ void __launch_bounds__(512) edge_score_k(const int* __restrict__ ei,
                                                    const float* __restrict__ PA,
                                                    const float* __restrict__ PB,
                                                    const float* __restrict__ Wm2,
                                                    const float* __restrict__ bm2,
                                                    float* __restrict__ out) {
    extern __shared__ float sm[];
    float* pa_s = sm;                     // 256*ESTRIDE
    float* pb_s = sm + 256 * ESTRIDE;     // 256*ESTRIDE
    __shared__ float wm2s[256];
    int g = blockIdx.x, tid = threadIdx.x;
    if (tid < 256) wm2s[tid] = Wm2[tid];
    int base = g * EPG;

    int r[8], c[8];
    float acc[8];
#pragma unroll
    for (int i = 0; i < 8; i++) {
        int j = tid + i * 512;
        r[i] = ei[base + j] - g * NPG;
        c[i] = ei[En + base + j] - g * NPG;
        acc[i] = 0.f;
    }

    for (int p = 0; p < 4; p++) {
        __syncthreads();
        for (int t = tid; t < 4096; t += 512) {
            int nd = t >> 4, kk = (t & 15) * 4;
            *(float4*)&pa_s[nd * ESTRIDE + kk] = *(const float4*)&PA[(g * NPG + nd) * 256 + p * 64 + kk];
            *(float4*)&pb_s[nd * ESTRIDE + kk] = *(const float4*)&PB[(g * NPG + nd) * 256 + p * 64 + kk];
        }
        __syncthreads();
        // kk-outer: hoist wm2 into registers, reuse across 8 edges
#pragma unroll 4
        for (int kk = 0; kk < 64; kk += 4) {
            float4 w4 = *(const float4*)&wm2s[p * 64 + kk];
#pragma unroll
            for (int i = 0; i < 8; i++) {
                float4 va = *(const float4*)&pa_s[r[i] * ESTRIDE + kk];
                float4 vb = *(const float4*)&pb_s[c[i] * ESTRIDE + kk];
                acc[i] += w4.x * fmaxf(va.x + vb.x, 0.f)
                        + w4.y * fmaxf(va.y + vb.y, 0.f)
                        + w4.z * fmaxf(va.z + vb.z, 0.f)
                        + w4.w * fmaxf(va.w + vb.w, 0.f);
            }
        }
    }
    float bb = bm2[0];
#pragma unroll
    for (int i = 0; i < 8; i++) out[base + tid + i * 512] = acc[i] + bb;
}

// ---------------- per-group stable bitonic argsort (desc score, ties asc idx) ----------------
__global__ void __launch_bounds__(1024) sort_k(const int* __restrict__ ei,
                                               float* __restrict__ out) {
    __shared__ unsigned long long keys[EPG];
    int g = blockIdx.x, tid = threadIdx.x;
    int base = g * EPG;
    for (int j = tid; j < EPG; j += 1024) {
        float s = out[base + j];
        unsigned int b = __float_as_uint(s);
        unsigned int enc = (b & 0x80000000u) ? ~b : (b | 0x80000000u);
        keys[j] = (((unsigned long long)(~enc)) << 32) | (unsigned int)j;
    }
    __syncthreads();
    for (int size = 2; size <= EPG; size <<= 1) {
        for (int stride = size >> 1; stride > 0; stride >>= 1) {
#pragma unroll 2
            for (int t = tid; t < EPG / 2; t += 1024) {
                int lo = ((t & ~(stride - 1)) << 1) | (t & (stride - 1));
                int hi = lo + stride;
                bool asc = ((lo & size) == 0);
                unsigned long long a = keys[lo], b = keys[hi];
                bool sw = asc ? (a > b) : (a < b);
                if (sw) { keys[lo] = b; keys[hi] = a; }
            }
            __syncthreads();
        }
    }
    for (int i2 = tid; i2 < EPG; i2 += 1024) {
        unsigned long long kv = keys[i2];
        int j = (int)(kv & 0xffffffffull);
        unsigned int enc = ~(unsigned int)(kv >> 32);
        unsigned int sb = (enc & 0x80000000u) ? (enc & 0x7fffffffu) : ~enc;
        float s = __uint_as_float(sb);
        int e = base + j;
        int rs = ei[e];
        int rd = ei[En + e];
        if (i2 < Kk) {
            int o = g * Kk + i2;
            out[OFF_CW + o] = s;
            g_keepnodes[o] = rs;
            g_keepnodes[GKn + o] = rd;
            g_presC[rs] = 1;
            g_presC[rd] = 1;
        } else {
            int o = g * Kk + (i2 - Kk);
            out[OFF_DW + o] = -s;
            g_dropnodes[o] = rs;
            g_dropnodes[GKn + o] = rd;
            g_presD[rs] = 1;
            g_presD[rd] = 1;
        }
    }
}

// ---------------- merged scans (y=0: causal, y=1: conf) ----------------
__global__ void __launch_bounds__(1024) scan1_k() {
    __shared__ int ws_[32];
    const int* pres = blockIdx.y ? g_presD : g_presC;
    int* nid = blockIdx.y ? g_nidD : g_nidC;
    int* bsum = blockIdx.y ? g_bsD : g_bsC;
    int i = blockIdx.x * 1024 + threadIdx.x;
    int x = pres[i];
    int v = warp_incl_scan(x);
    int w = threadIdx.x >> 5, lane = threadIdx.x & 31;
    if (lane == 31) ws_[w] = v;
    __syncthreads();
    if (w == 0) { int t = ws_[lane]; t = warp_incl_scan(t); ws_[lane] = t; }
    __syncthreads();
    if (w > 0) v += ws_[w - 1];
    nid[i] = v;
    if (threadIdx.x == 1023) bsum[blockIdx.x] = v;
}

__global__ void scan2_k() {
    int* bsum = (threadIdx.x >= 32) ? g_bsD : g_bsC;
    int idx = threadIdx.x & 31;
    int x = bsum[idx];
    int v = warp_incl_scan(x);
    bsum[idx] = v - x;
}

__global__ void __launch_bounds__(1024) scan3_k(float* __restrict__ out) {
    const int* pres = blockIdx.y ? g_presD : g_presC;
    int* nid = blockIdx.y ? g_nidD : g_nidC;
    const int* bsum = blockIdx.y ? g_bsD : g_bsC;
    float* maskOut = out + (blockIdx.y ? OFF_FMASK : OFF_CMASK);
    int i = blockIdx.x * 1024 + threadIdx.x;
    nid[i] = nid[i] + bsum[blockIdx.x] - 1;
    maskOut[i] = (float)pres[i];
}

// ---------------- final relabeled-edge gather ----------------
__global__ void gather_k(float* __restrict__ out) {
    int i = blockIdx.x * blockDim.x + threadIdx.x;
    if (i >= 2 * GKn) return;
    out[OFF_CEI + i] = (float)g_nidC[g_keepnodes[i]];
    out[OFF_FEI + i] = (float)g_nidD[g_dropnodes[i]];
}

// ---------------- host launch ----------------
extern "C" void kernel_launch(void* const* d_in, const int* in_sizes, int n_in,
                              void* d_out, int out_size) {
    const float* x   = (const float*)d_in[0];
    const float* ea  = (const float*)d_in[1];
    const float* W11 = (const float*)d_in[2];
    const float* b11 = (const float*)d_in[3];
    const float* W12 = (const float*)d_in[4];
    const float* W13 = (const float*)d_in[5];
    const float* b13 = (const float*)d_in[6];
    const float* W21 = (const float*)d_in[7];
    const float* b21 = (const float*)d_in[8];
    const float* W22 = (const float*)d_in[9];
    const float* W23 = (const float*)d_in[10];
    const float* b23 = (const float*)d_in[11];
    const float* Wm1 = (const float*)d_in[12];
    const float* bm1 = (const float*)d_in[13];
    const float* Wm2 = (const float*)d_in[14];
    const float* bm2 = (const float*)d_in[15];
    const int*   ei  = (const int*)d_in[16];   // int32 (JAX x64 disabled)
    float* out = (float*)d_out;

    float *A, *B, *C, *H1, *H2, *PA, *PB;
    cudaGetSymbolAddress((void**)&A, g_A);
    cudaGetSymbolAddress((void**)&B, g_B);
    cudaGetSymbolAddress((void**)&C, g_C);
    cudaGetSymbolAddress((void**)&H1, g_H1);
    cudaGetSymbolAddress((void**)&H2, g_H2);
    cudaGetSymbolAddress((void**)&PA, g_PA);
    cudaGetSymbolAddress((void**)&PB, g_PB);

    const int g3Smem  = 4 * 4096 * sizeof(float);          // 64 KB
    const int agSmem  = NPG * 64 * sizeof(float);          // 64 KB
    const int esSmem  = 2 * 256 * ESTRIDE * sizeof(float); // 136 KB
    cudaFuncSetAttribute(gemm3_k, cudaFuncAttributeMaxDynamicSharedMemorySize, g3Smem);
    cudaFuncSetAttribute(aggc2_k, cudaFuncAttributeMaxDynamicSharedMemorySize, agSmem);
    cudaFuncSetAttribute(edge_score_k, cudaFuncAttributeMaxDynamicSharedMemorySize, esSmem);

    csr_build_k<<<Gn, 256>>>(ei, ea);

    // ---- leconv 1 ----
    gemm3_k<<<Nn / 64, 256, g3Smem>>>(x, W11, b11, W12, W13, b13);
    aggc2_k<<<Gn, 256, agSmem>>>(A, B, C, H1, 1);

    // ---- leconv 2 ----
    gemm3_k<<<Nn / 64, 256, g3Smem>>>(H1, W21, b21, W22, W23, b23);
    aggc2_k<<<Gn, 256, agSmem>>>(A, B, C, H2, 0);

    // ---- MLP node projections (PA | PB) ----
    gemmP_k<<<dim3(Nn / 64, 8), 128>>>(H2, Wm1, bm1);

    // ---- per-edge scores ----
    edge_score_k<<<Gn, 512, esSmem>>>(ei, PA, PB, Wm2, bm2, out);

    // ---- per-group sort + keep/drop split ----
    sort_k<<<Gn, 1024>>>(ei, out);

    // ---- relabel scans (both graphs in one launch each) ----
    scan1_k<<<dim3(32, 2), 1024>>>();
    scan2_k<<<1, 64>>>();
    scan3_k<<<dim3(32, 2), 1024>>>(out);

    // ---- relabeled edge index gather ----
    gather_k<<<(2 * GKn) / 256, 256>>>(out);
}

// round 5
// speedup vs baseline: 1.3076x; 1.3076x over previous
#include <cuda_runtime.h>

// ---------------- problem constants ----------------
#define Gn   128
#define NPG  256
#define EPG  4096
#define Nn   (Gn*NPG)          // 32768 nodes
#define En   (Gn*EPG)          // 524288 edges
#define Kk   2048              // kept edges per group
#define GKn  (Gn*Kk)           // 262144

// output layout (all f32, flattened tuple in reference order)
#define OFF_SCORE 0
#define OFF_CW    (En)
#define OFF_DW    (En + GKn)
#define OFF_CEI   (En + 2*GKn)
#define OFF_FEI   (En + 4*GKn)
#define OFF_CMASK (En + 6*GKn)
#define OFF_FMASK (En + 6*GKn + Nn)

// ---------------- device scratch ----------------
__device__ float g_A[Nn*64];
__device__ float g_B[Nn*64];
__device__ float g_C[Nn*64];
__device__ float g_H1[Nn*64];
__device__ float g_H2[Nn*64];
__device__ float g_PA[Nn*256];
__device__ float g_PB[Nn*256];
__device__ int   g_rows[En];      // LOCAL src node id (0..255)
__device__ float g_ews[En];
__device__ int   g_start[Nn];
__device__ int   g_keepnodes[2*GKn];
__device__ int   g_dropnodes[2*GKn];
__device__ int   g_presC[Nn];
__device__ int   g_presD[Nn];
__device__ int   g_nidC[Nn];
__device__ int   g_nidD[Nn];
__device__ int   g_bsC[32];
__device__ int   g_bsD[32];

// ---------------- helpers ----------------
__device__ __forceinline__ int warp_incl_scan(int v) {
    int lane = threadIdx.x & 31;
#pragma unroll
    for (int o = 1; o < 32; o <<= 1) {
        int t = __shfl_up_sync(0xffffffffu, v, o);
        if (lane >= o) v += t;
    }
    return v;
}

__device__ __forceinline__ void fma2(unsigned long long& d, unsigned long long a, unsigned long long b) {
    asm("fma.rn.f32x2 %0, %1, %2, %0;" : "+l"(d) : "l"(a), "l"(b));
}
__device__ __forceinline__ float2 up2(unsigned long long v) {
    float2 f;
    asm("mov.b64 {%0,%1}, %2;" : "=f"(f.x), "=f"(f.y) : "l"(v));
    return f;
}
__device__ __forceinline__ float red2(unsigned long long v) {
    float2 f = up2(v);
    return f.x + f.y;
}

// ---------------- deterministic per-group CSR (counting sort by dst) + zero pres ----------------
__global__ void __launch_bounds__(256) csr_build_k(const int* __restrict__ ei,
                                                   const float* __restrict__ ea) {
    __shared__ int hist[8][256];
    __shared__ int wsums[8];
    int g = blockIdx.x, tid = threadIdx.x;
    int w = tid >> 5, lane = tid & 31;
    int base = g * EPG;

    g_presC[g * NPG + tid] = 0;
    g_presD[g * NPG + tid] = 0;

#pragma unroll
    for (int i = 0; i < 8; i++) hist[i][tid] = 0;
    __syncthreads();

    for (int rnd = 0; rnd < 16; rnd++) {
        int j = w * 512 + rnd * 32 + lane;
        int c = ei[En + base + j] - g * NPG;
        atomicAdd(&hist[w][c], 1);
    }
    __syncthreads();

    int s = 0;
#pragma unroll
    for (int i = 0; i < 8; i++) { int h = hist[i][tid]; hist[i][tid] = s; s += h; }
    int incl = warp_incl_scan(s);
    if (lane == 31) wsums[w] = incl;
    __syncthreads();
    if (tid == 0) { int a = 0; for (int i = 0; i < 8; i++) { int t = wsums[i]; wsums[i] = a; a += t; } }
    __syncthreads();
    int excl_c = incl - s + wsums[w];
    g_start[g * NPG + tid] = base + excl_c;
#pragma unroll
    for (int i = 0; i < 8; i++) hist[i][tid] += excl_c;
    __syncthreads();

    for (int rnd = 0; rnd < 16; rnd++) {
        int j = w * 512 + rnd * 32 + lane;
        int r = ei[base + j] - g * NPG;          // LOCAL id
        int c = ei[En + base + j] - g * NPG;
        float wv = ea[base + j];
        unsigned mask = __match_any_sync(0xffffffffu, c);
        int rank = __popc(mask & ((1u << lane) - 1u));
        int cur = hist[w][c];
        __syncwarp();
        if (lane == (__ffs(mask) - 1)) hist[w][c] = cur + __popc(mask);
        g_rows[base + cur + rank] = r;
        g_ews[base + cur + rank]  = wv;
        __syncwarp();
    }
}

// ---------------- universal GEMM core: k-pair packed f32x2 dot, 512 thr, 64x64 tile ----------
// Xs: [v][k] stride 68, Ws: [f][k] stride 68. Thread: 4v x 2f, acc u64 per output.
#define GSTR 68

// leconv layer: grid (Nn/64, 3): y=0 -> A=X@W1'+b1, y=1 -> B=X@W2', y=2 -> C=X@W3'+b3
__global__ void __launch_bounds__(512) gemmL_k(const float* __restrict__ X,
                                               const float* __restrict__ W1,
                                               const float* __restrict__ b1,
                                               const float* __restrict__ W2,
                                               const float* __restrict__ W3,
                                               const float* __restrict__ b3) {
    __shared__ __align__(16) float Xs[64 * GSTR];
    __shared__ __align__(16) float Ws[64 * GSTR];
    int tid = threadIdx.x;
    int vtile = blockIdx.x * 64;
    int m = blockIdx.y;
    const float* W = (m == 0) ? W1 : ((m == 1) ? W2 : W3);
    const float* bias = (m == 0) ? b1 : ((m == 2) ? b3 : nullptr);
    float* Y = (m == 0) ? g_A : ((m == 1) ? g_B : g_C);

    for (int t = tid; t < 1024; t += 512) {
        int row = t >> 4, kq = (t & 15) * 4;
        *(float4*)&Xs[row * GSTR + kq] = *(const float4*)&X[(vtile + row) * 64 + kq];
        *(float4*)&Ws[row * GSTR + kq] = *(const float4*)&W[row * 64 + kq];
    }
    __syncthreads();

    int tv = tid >> 5, tf = tid & 31;
    int v0 = tv * 4, f0 = tf * 2;
    unsigned long long acc[4][2];
#pragma unroll
    for (int v = 0; v < 4; v++) { acc[v][0] = 0ull; acc[v][1] = 0ull; }

#pragma unroll
    for (int k = 0; k < 64; k += 4) {
        ulonglong2 wv0 = *(const ulonglong2*)&Ws[f0 * GSTR + k];
        ulonglong2 wv1 = *(const ulonglong2*)&Ws[(f0 + 1) * GSTR + k];
#pragma unroll
        for (int v = 0; v < 4; v++) {
            ulonglong2 xv = *(const ulonglong2*)&Xs[(v0 + v) * GSTR + k];
            fma2(acc[v][0], xv.x, wv0.x); fma2(acc[v][0], xv.y, wv0.y);
            fma2(acc[v][1], xv.x, wv1.x); fma2(acc[v][1], xv.y, wv1.y);
        }
    }

    float b0 = 0.f, b1v = 0.f;
    if (bias) { b0 = bias[f0]; b1v = bias[f0 + 1]; }
#pragma unroll
    for (int v = 0; v < 4; v++) {
        float2 o = make_float2(red2(acc[v][0]) + b0, red2(acc[v][1]) + b1v);
        *(float2*)&Y[(vtile + v0 + v) * 64 + f0] = o;
    }
}

// MLP projection: grid (Nn/64, 8): y<4 -> PA tile y, y>=4 -> PB tile y-4. Wm1 rows stride 128.
__global__ void __launch_bounds__(512) gemmM_k(const float* __restrict__ X,
                                               const float* __restrict__ Wm1,
                                               const float* __restrict__ bm1) {
    __shared__ __align__(16) float Xs[64 * GSTR];
    __shared__ __align__(16) float Ws[64 * GSTR];
    int tid = threadIdx.x;
    int vtile = blockIdx.x * 64;
    int y = blockIdx.y;
    int isB = (y >= 4);
    int ftile = (y & 3) * 64;
    int koff = isB ? 64 : 0;
    float* Y = isB ? g_PB : g_PA;

    for (int t = tid; t < 1024; t += 512) {
        int row = t >> 4, kq = (t & 15) * 4;
        *(float4*)&Xs[row * GSTR + kq] = *(const float4*)&X[(vtile + row) * 64 + kq];
        *(float4*)&Ws[row * GSTR + kq] = *(const float4*)&Wm1[(ftile + row) * 128 + koff + kq];
    }
    __syncthreads();

    int tv = tid >> 5, tf = tid & 31;
    int v0 = tv * 4, f0 = tf * 2;
    unsigned long long acc[4][2];
#pragma unroll
    for (int v = 0; v < 4; v++) { acc[v][0] = 0ull; acc[v][1] = 0ull; }

#pragma unroll
    for (int k = 0; k < 64; k += 4) {
        ulonglong2 wv0 = *(const ulonglong2*)&Ws[f0 * GSTR + k];
        ulonglong2 wv1 = *(const ulonglong2*)&Ws[(f0 + 1) * GSTR + k];
#pragma unroll
        for (int v = 0; v < 4; v++) {
            ulonglong2 xv = *(const ulonglong2*)&Xs[(v0 + v) * GSTR + k];
            fma2(acc[v][0], xv.x, wv0.x); fma2(acc[v][0], xv.y, wv0.y);
            fma2(acc[v][1], xv.x, wv1.x); fma2(acc[v][1], xv.y, wv1.y);
        }
    }

    float b0 = 0.f, b1v = 0.f;
    if (!isB) { b0 = bm1[ftile + f0]; b1v = bm1[ftile + f0 + 1]; }
#pragma unroll
    for (int v = 0; v < 4; v++) {
        float2 o = make_float2(red2(acc[v][0]) + b0, red2(acc[v][1]) + b1v);
        *(float2*)&Y[(vtile + v0 + v) * 256 + ftile + f0] = o;
    }
}

// ---------------- gather-aggregate + combine (R3-proven shape, local rows) -------------
__global__ void aggc_k(const float* __restrict__ A, const float* __restrict__ B,
                       const float* __restrict__ C, float* __restrict__ H, int doRelu) {
    int warp = blockIdx.x * (blockDim.x >> 5) + (threadIdx.x >> 5);
    int lane = threadIdx.x & 31;
    if (warp >= Nn) return;
    int v = warp;
    int s = g_start[v];
    int g = v >> 8;
    int e = ((v & 255) == 255) ? (g * EPG + EPG) : g_start[v + 1];
    int abase = g * NPG * 64;
    float2 acc = make_float2(0.f, 0.f);
    float ws = 0.f;
    for (int i = s; i < e; i++) {
        int r = g_rows[i];
        float w = g_ews[i];
        float2 a = *(const float2*)&A[abase + r * 64 + lane * 2];
        acc.x += w * a.x;
        acc.y += w * a.y;
        ws += w;
    }
    float2 bv = *(const float2*)&B[v * 64 + lane * 2];
    float2 cv = *(const float2*)&C[v * 64 + lane * 2];
    float hx = acc.x - ws * bv.x + cv.x;
    float hy = acc.y - ws * bv.y + cv.y;
    if (doRelu) { hx = fmaxf(hx, 0.f); hy = fmaxf(hy, 0.f); }
    *(float2*)&H[v * 64 + lane * 2] = make_float2(hx, hy);
}

// ---------------- per-edge score: smem-staged relu-dot, kk-outer ----------------
#define ESTRIDE 68
__global__ void __launch_bounds__(512) edge_score_k(const int* __restrict__ ei,
                                                    const float* __restrict__ PA,
                                                    const float* __restrict__ PB,
                                                    const float* __restrict__ Wm2,
                                                    const float* __restrict__ bm2,
                                                    float* __restrict__ out) {
    extern __shared__ float sm[];
    float* pa_s = sm;                     // 256*ESTRIDE
    float* pb_s = sm + 256 * ESTRIDE;     // 256*ESTRIDE
    __shared__ float wm2s[256];
    int g = blockIdx.x, tid = threadIdx.x;
    if (tid < 256) wm2s[tid] = Wm2[tid];
    int base = g * EPG;

    int r[8], c[8];
    float acc[8];
#pragma unroll
    for (int i = 0; i < 8; i++) {
        int j = tid + i * 512;
        r[i] = ei[base + j] - g * NPG;
        c[i] = ei[En + base + j] - g * NPG;
        acc[i] = 0.f;
    }

    for (int p = 0; p < 4; p++) {
        __syncthreads();
        for (int t = tid; t < 4096; t += 512) {
            int nd = t >> 4, kk = (t & 15) * 4;
            *(float4*)&pa_s[nd * ESTRIDE + kk] = *(const float4*)&PA[(g * NPG + nd) * 256 + p * 64 + kk];
            *(float4*)&pb_s[nd * ESTRIDE + kk] = *(const float4*)&PB[(g * NPG + nd) * 256 + p * 64 + kk];
        }
        __syncthreads();
#pragma unroll 4
        for (int kk = 0; kk < 64; kk += 4) {
            float4 w4 = *(const float4*)&wm2s[p * 64 + kk];
#pragma unroll
            for (int i = 0; i < 8; i++) {
                float4 va = *(const float4*)&pa_s[r[i] * ESTRIDE + kk];
                float4 vb = *(const float4*)&pb_s[c[i] * ESTRIDE + kk];
                acc[i] += w4.x * fmaxf(va.x + vb.x, 0.f)
                        + w4.y * fmaxf(va.y + vb.y, 0.f)
                        + w4.z * fmaxf(va.z + vb.z, 0.f)
                        + w4.w * fmaxf(va.w + vb.w, 0.f);
            }
        }
    }
    float bb = bm2[0];
#pragma unroll
    for (int i = 0; i < 8; i++) out[base + tid + i * 512] = acc[i] + bb;
}

// ---------------- per-group stable bitonic argsort (desc score, ties asc idx) ----------------
__global__ void __launch_bounds__(1024) sort_k(const int* __restrict__ ei,
                                               float* __restrict__ out) {
    __shared__ unsigned long long keys[EPG];
    int g = blockIdx.x, tid = threadIdx.x;
    int base = g * EPG;
    for (int j = tid; j < EPG; j += 1024) {
        float s = out[base + j];
        unsigned int b = __float_as_uint(s);
        unsigned int enc = (b & 0x80000000u) ? ~b : (b | 0x80000000u);
        keys[j] = (((unsigned long long)(~enc)) << 32) | (unsigned int)j;
    }
    __syncthreads();
    for (int size = 2; size <= EPG; size <<= 1) {
        for (int stride = size >> 1; stride > 0; stride >>= 1) {
#pragma unroll 2
            for (int t = tid; t < EPG / 2; t += 1024) {
                int lo = ((t & ~(stride - 1)) << 1) | (t & (stride - 1));
                int hi = lo + stride;
                bool asc = ((lo & size) == 0);
                unsigned long long a = keys[lo], b = keys[hi];
                bool sw = asc ? (a > b) : (a < b);
                if (sw) { keys[lo] = b; keys[hi] = a; }
            }
            __syncthreads();
        }
    }
    for (int i2 = tid; i2 < EPG; i2 += 1024) {
        unsigned long long kv = keys[i2];
        int j = (int)(kv & 0xffffffffull);
        unsigned int enc = ~(unsigned int)(kv >> 32);
        unsigned int sb = (enc & 0x80000000u) ? (enc & 0x7fffffffu) : ~enc;
        float s = __uint_as_float(sb);
        int e = base + j;
        int rs = ei[e];
        int rd = ei[En + e];
        if (i2 < Kk) {
            int o = g * Kk + i2;
            out[OFF_CW + o] = s;
            g_keepnodes[o] = rs;
            g_keepnodes[GKn + o] = rd;
            g_presC[rs] = 1;
            g_presC[rd] = 1;
        } else {
            int o = g * Kk + (i2 - Kk);
            out[OFF_DW + o] = -s;
            g_dropnodes[o] = rs;
            g_dropnodes[GKn + o] = rd;
            g_presD[rs] = 1;
            g_presD[rd] = 1;
        }
    }
}

// ---------------- merged scans (y=0: causal, y=1: conf) ----------------
__global__ void __launch_bounds__(1024) scan1_k() {
    __shared__ int ws_[32];
    const int* pres = blockIdx.y ? g_presD : g_presC;
    int* nid = blockIdx.y ? g_nidD : g_nidC;
    int* bsum = blockIdx.y ? g_bsD : g_bsC;
    int i = blockIdx.x * 1024 + threadIdx.x;
    int x = pres[i];
    int v = warp_incl_scan(x);
    int w = threadIdx.x >> 5, lane = threadIdx.x & 31;
    if (lane == 31) ws_[w] = v;
    __syncthreads();
    if (w == 0) { int t = ws_[lane]; t = warp_incl_scan(t); ws_[lane] = t; }
    __syncthreads();
    if (w > 0) v += ws_[w - 1];
    nid[i] = v;
    if (threadIdx.x == 1023) bsum[blockIdx.x] = v;
}

__global__ void scan2_k() {
    int* bsum = (threadIdx.x >= 32) ? g_bsD : g_bsC;
    int idx = threadIdx.x & 31;
    int x = bsum[idx];
    int v = warp_incl_scan(x);
    bsum[idx] = v - x;
}

__global__ void __launch_bounds__(1024) scan3_k(float* __restrict__ out) {
    const int* pres = blockIdx.y ? g_presD : g_presC;
    int* nid = blockIdx.y ? g_nidD : g_nidC;
    const int* bsum = blockIdx.y ? g_bsD : g_bsC;
    float* maskOut = out + (blockIdx.y ? OFF_FMASK : OFF_CMASK);
    int i = blockIdx.x * 1024 + threadIdx.x;
    nid[i] = nid[i] + bsum[blockIdx.x] - 1;
    maskOut[i] = (float)pres[i];
}

// ---------------- final relabeled-edge gather ----------------
__global__ void gather_k(float* __restrict__ out) {
    int i = blockIdx.x * blockDim.x + threadIdx.x;
    if (i >= 2 * GKn) return;
    out[OFF_CEI + i] = (float)g_nidC[g_keepnodes[i]];
    out[OFF_FEI + i] = (float)g_nidD[g_dropnodes[i]];
}

// ---------------- host launch ----------------
extern "C" void kernel_launch(void* const* d_in, const int* in_sizes, int n_in,
                              void* d_out, int out_size) {
    const float* x   = (const float*)d_in[0];
    const float* ea  = (const float*)d_in[1];
    const float* W11 = (const float*)d_in[2];
    const float* b11 = (const float*)d_in[3];
    const float* W12 = (const float*)d_in[4];
    const float* W13 = (const float*)d_in[5];
    const float* b13 = (const float*)d_in[6];
    const float* W21 = (const float*)d_in[7];
    const float* b21 = (const float*)d_in[8];
    const float* W22 = (const float*)d_in[9];
    const float* W23 = (const float*)d_in[10];
    const float* b23 = (const float*)d_in[11];
    const float* Wm1 = (const float*)d_in[12];
    const float* bm1 = (const float*)d_in[13];
    const float* Wm2 = (const float*)d_in[14];
    const float* bm2 = (const float*)d_in[15];
    const int*   ei  = (const int*)d_in[16];   // int32 (JAX x64 disabled)
    float* out = (float*)d_out;

    float *A, *B, *C, *H1, *H2, *PA, *PB;
    cudaGetSymbolAddress((void**)&A, g_A);
    cudaGetSymbolAddress((void**)&B, g_B);
    cudaGetSymbolAddress((void**)&C, g_C);
    cudaGetSymbolAddress((void**)&H1, g_H1);
    cudaGetSymbolAddress((void**)&H2, g_H2);
    cudaGetSymbolAddress((void**)&PA, g_PA);
    cudaGetSymbolAddress((void**)&PB, g_PB);

    const int esSmem = 2 * 256 * ESTRIDE * sizeof(float); // 136 KB
    cudaFuncSetAttribute(edge_score_k, cudaFuncAttributeMaxDynamicSharedMemorySize, esSmem);

    csr_build_k<<<Gn, 256>>>(ei, ea);

    // ---- leconv 1 ----
    gemmL_k<<<dim3(Nn / 64, 3), 512>>>(x, W11, b11, W12, W13, b13);
    aggc_k<<<Nn / 8, 256>>>(A, B, C, H1, 1);

    // ---- leconv 2 ----
    gemmL_k<<<dim3(Nn / 64, 3), 512>>>(H1, W21, b21, W22, W23, b23);
    aggc_k<<<Nn / 8, 256>>>(A, B, C, H2, 0);

    // ---- MLP node projections (PA | PB) ----
    gemmM_k<<<dim3(Nn / 64, 8), 512>>>(H2, Wm1, bm1);

    // ---- per-edge scores ----
    edge_score_k<<<Gn, 512, esSmem>>>(ei, PA, PB, Wm2, bm2, out);

    // ---- per-group sort + keep/drop split ----
    sort_k<<<Gn, 1024>>>(ei, out);

    // ---- relabel scans (both graphs, merged) ----
    scan1_k<<<dim3(32, 2), 1024>>>();
    scan2_k<<<1, 64>>>();
    scan3_k<<<dim3(32, 2), 1024>>>(out);

    // ---- relabeled edge index gather ----
    gather_k<<<(2 * GKn) / 256, 256>>>(out);
}

// round 6
// speedup vs baseline: 1.6850x; 1.2887x over previous
#include <cuda_runtime.h>

// ---------------- problem constants ----------------
#define Gn   128
#define NPG  256
#define EPG  4096
#define Nn   (Gn*NPG)          // 32768 nodes
#define En   (Gn*EPG)          // 524288 edges
#define Kk   2048              // kept edges per group
#define GKn  (Gn*Kk)           // 262144

// output layout (all f32, flattened tuple in reference order)
#define OFF_SCORE 0
#define OFF_CW    (En)
#define OFF_DW    (En + GKn)
#define OFF_CEI   (En + 2*GKn)
#define OFF_FEI   (En + 4*GKn)
#define OFF_CMASK (En + 6*GKn)
#define OFF_FMASK (En + 6*GKn + Nn)

// ---------------- device scratch ----------------
__device__ float g_A[Nn*64];
__device__ float g_B[Nn*64];
__device__ float g_C[Nn*64];
__device__ float g_H1[Nn*64];
__device__ float g_H2[Nn*64];
__device__ float g_PA[Nn*256];
__device__ float g_PB[Nn*256];
__device__ int   g_rows[En];      // LOCAL src node id (0..255)
__device__ float g_ews[En];
__device__ int   g_start[Nn];
__device__ int   g_keepnodes[2*GKn];
__device__ int   g_dropnodes[2*GKn];
__device__ int   g_presC[Nn];
__device__ int   g_presD[Nn];
__device__ int   g_nidC[Nn];
__device__ int   g_nidD[Nn];
__device__ int   g_bsC[32];
__device__ int   g_bsD[32];

// ---------------- helpers ----------------
__device__ __forceinline__ int warp_incl_scan(int v) {
    int lane = threadIdx.x & 31;
#pragma unroll
    for (int o = 1; o < 32; o <<= 1) {
        int t = __shfl_up_sync(0xffffffffu, v, o);
        if (lane >= o) v += t;
    }
    return v;
}

__device__ __forceinline__ void fma2(unsigned long long& d, unsigned long long a, unsigned long long b) {
    asm("fma.rn.f32x2 %0, %1, %2, %0;" : "+l"(d) : "l"(a), "l"(b));
}
__device__ __forceinline__ float2 up2(unsigned long long v) {
    float2 f;
    asm("mov.b64 {%0,%1}, %2;" : "=f"(f.x), "=f"(f.y) : "l"(v));
    return f;
}
__device__ __forceinline__ float red2(unsigned long long v) {
    float2 f = up2(v);
    return f.x + f.y;
}

// ---------------- deterministic per-group CSR (counting sort by dst) + zero pres ----------------
__global__ void __launch_bounds__(256) csr_build_k(const int* __restrict__ ei,
                                                   const float* __restrict__ ea) {
    __shared__ int hist[8][256];
    __shared__ int wsums[8];
    int g = blockIdx.x, tid = threadIdx.x;
    int w = tid >> 5, lane = tid & 31;
    int base = g * EPG;

    g_presC[g * NPG + tid] = 0;
    g_presD[g * NPG + tid] = 0;

#pragma unroll
    for (int i = 0; i < 8; i++) hist[i][tid] = 0;
    __syncthreads();

    for (int rnd = 0; rnd < 16; rnd++) {
        int j = w * 512 + rnd * 32 + lane;
        int c = ei[En + base + j] - g * NPG;
        atomicAdd(&hist[w][c], 1);
    }
    __syncthreads();

    int s = 0;
#pragma unroll
    for (int i = 0; i < 8; i++) { int h = hist[i][tid]; hist[i][tid] = s; s += h; }
    int incl = warp_incl_scan(s);
    if (lane == 31) wsums[w] = incl;
    __syncthreads();
    if (tid == 0) { int a = 0; for (int i = 0; i < 8; i++) { int t = wsums[i]; wsums[i] = a; a += t; } }
    __syncthreads();
    int excl_c = incl - s + wsums[w];
    g_start[g * NPG + tid] = base + excl_c;
#pragma unroll
    for (int i = 0; i < 8; i++) hist[i][tid] += excl_c;
    __syncthreads();

    for (int rnd = 0; rnd < 16; rnd++) {
        int j = w * 512 + rnd * 32 + lane;
        int r = ei[base + j] - g * NPG;          // LOCAL id
        int c = ei[En + base + j] - g * NPG;
        float wv = ea[base + j];
        unsigned mask = __match_any_sync(0xffffffffu, c);
        int rank = __popc(mask & ((1u << lane) - 1u));
        int cur = hist[w][c];
        __syncwarp();
        if (lane == (__ffs(mask) - 1)) hist[w][c] = cur + __popc(mask);
        g_rows[base + cur + rank] = r;
        g_ews[base + cur + rank]  = wv;
        __syncwarp();
    }
}

// ================= swizzled f32x2 GEMM core =================
// Tiles: X [64v x 64k], W [64f x 64k], both stored k-major with 16B-granule XOR swizzle:
//   element (row, k) lives at base[row*64 + ((kg ^ (row & 15)) << 2) + (k & 3)], kg = k >> 2.
// 256 threads: tf = tid & 15 owns f rows {tf+16j}, tv = tid >> 4 owns v rows {tv+16i}.
// Per 4-k granule: 4 W LDS.128 (16 distinct granules across half-warp -> conflict-free)
//                + 4 X LDS.128 (broadcast). 32 fma2 per 8 LDS.128.

__device__ __forceinline__ void gemm_core(const float* __restrict__ Xs,
                                          const float* __restrict__ Ws,
                                          int tf, int tv,
                                          unsigned long long acc[4][4]) {
#pragma unroll 4
    for (int gk = 0; gk < 16; gk++) {
        int xoff = (gk ^ tv) << 2;
        int woff = (gk ^ tf) << 2;
        ulonglong2 xq[4], wq[4];
#pragma unroll
        for (int i = 0; i < 4; i++)
            xq[i] = *(const ulonglong2*)&Xs[(tv + 16 * i) * 64 + xoff];
#pragma unroll
        for (int j = 0; j < 4; j++)
            wq[j] = *(const ulonglong2*)&Ws[(tf + 16 * j) * 64 + woff];
#pragma unroll
        for (int i = 0; i < 4; i++)
#pragma unroll
            for (int j = 0; j < 4; j++) {
                fma2(acc[i][j], xq[i].x, wq[j].x);
                fma2(acc[i][j], xq[i].y, wq[j].y);
            }
    }
}

// load a 64x64 tile (row stride lds in gmem) into swizzled smem
__device__ __forceinline__ void load_tile(float* __restrict__ dst,
                                          const float* __restrict__ src, int lds,
                                          int tid) {
#pragma unroll
    for (int t = tid; t < 1024; t += 256) {
        int row = t >> 4, kg = t & 15;
        *(float4*)&dst[row * 64 + ((kg ^ (row & 15)) << 2)] =
            *(const float4*)&src[row * lds + kg * 4];
    }
}

// leconv layer: grid (Nn/64, 3): y=0 -> A=X@W1'+b1, y=1 -> B=X@W2', y=2 -> C=X@W3'+b3
__global__ void __launch_bounds__(256) gemmL_k(const float* __restrict__ X,
                                               const float* __restrict__ W1,
                                               const float* __restrict__ b1,
                                               const float* __restrict__ W2,
                                               const float* __restrict__ W3,
                                               const float* __restrict__ b3) {
    __shared__ __align__(16) float Xs[64 * 64];
    __shared__ __align__(16) float Ws[64 * 64];
    int tid = threadIdx.x;
    int vtile = blockIdx.x * 64;
    int m = blockIdx.y;
    const float* W = (m == 0) ? W1 : ((m == 1) ? W2 : W3);
    const float* bias = (m == 0) ? b1 : ((m == 2) ? b3 : nullptr);
    float* Y = (m == 0) ? g_A : ((m == 1) ? g_B : g_C);

    load_tile(Xs, X + vtile * 64, 64, tid);
    load_tile(Ws, W, 64, tid);
    __syncthreads();

    int tf = tid & 15, tv = tid >> 4;
    unsigned long long acc[4][4];
#pragma unroll
    for (int i = 0; i < 4; i++)
#pragma unroll
        for (int j = 0; j < 4; j++) acc[i][j] = 0ull;

    gemm_core(Xs, Ws, tf, tv, acc);

    float bj[4] = {0.f, 0.f, 0.f, 0.f};
    if (bias) {
#pragma unroll
        for (int j = 0; j < 4; j++) bj[j] = bias[tf + 16 * j];
    }
#pragma unroll
    for (int i = 0; i < 4; i++)
#pragma unroll
        for (int j = 0; j < 4; j++)
            Y[(vtile + tv + 16 * i) * 64 + tf + 16 * j] = red2(acc[i][j]) + bj[j];
}

// MLP projection: grid (Nn/64, 8): y<4 -> PA tile y, y>=4 -> PB tile y-4. Wm1 rows stride 128.
__global__ void __launch_bounds__(256) gemmM_k(const float* __restrict__ X,
                                               const float* __restrict__ Wm1,
                                               const float* __restrict__ bm1) {
    __shared__ __align__(16) float Xs[64 * 64];
    __shared__ __align__(16) float Ws[64 * 64];
    int tid = threadIdx.x;
    int vtile = blockIdx.x * 64;
    int y = blockIdx.y;
    int isB = (y >= 4);
    int ftile = (y & 3) * 64;
    int koff = isB ? 64 : 0;
    float* Y = isB ? g_PB : g_PA;

    load_tile(Xs, X + vtile * 64, 64, tid);
    load_tile(Ws, Wm1 + ftile * 128 + koff, 128, tid);
    __syncthreads();

    int tf = tid & 15, tv = tid >> 4;
    unsigned long long acc[4][4];
#pragma unroll
    for (int i = 0; i < 4; i++)
#pragma unroll
        for (int j = 0; j < 4; j++) acc[i][j] = 0ull;

    gemm_core(Xs, Ws, tf, tv, acc);

    float bj[4] = {0.f, 0.f, 0.f, 0.f};
    if (!isB) {
#pragma unroll
        for (int j = 0; j < 4; j++) bj[j] = bm1[ftile + tf + 16 * j];
    }
#pragma unroll
    for (int i = 0; i < 4; i++)
#pragma unroll
        for (int j = 0; j < 4; j++)
            Y[(vtile + tv + 16 * i) * 256 + ftile + tf + 16 * j] = red2(acc[i][j]) + bj[j];
}

// ---------------- gather-aggregate + combine (R3-proven shape, local rows) -------------
__global__ void aggc_k(const float* __restrict__ A, const float* __restrict__ B,
                       const float* __restrict__ C, float* __restrict__ H, int doRelu) {
    int warp = blockIdx.x * (blockDim.x >> 5) + (threadIdx.x >> 5);
    int lane = threadIdx.x & 31;
    if (warp >= Nn) return;
    int v = warp;
    int s = g_start[v];
    int g = v >> 8;
    int e = ((v & 255) == 255) ? (g * EPG + EPG) : g_start[v + 1];
    int abase = g * NPG * 64;
    float2 acc = make_float2(0.f, 0.f);
    float ws = 0.f;
    for (int i = s; i < e; i++) {
        int r = g_rows[i];
        float w = g_ews[i];
        float2 a = *(const float2*)&A[abase + r * 64 + lane * 2];
        acc.x += w * a.x;
        acc.y += w * a.y;
        ws += w;
    }
    float2 bv = *(const float2*)&B[v * 64 + lane * 2];
    float2 cv = *(const float2*)&C[v * 64 + lane * 2];
    float hx = acc.x - ws * bv.x + cv.x;
    float hy = acc.y - ws * bv.y + cv.y;
    if (doRelu) { hx = fmaxf(hx, 0.f); hy = fmaxf(hy, 0.f); }
    *(float2*)&H[v * 64 + lane * 2] = make_float2(hx, hy);
}

// ---------------- per-edge score: smem-staged relu-dot, kk-outer ----------------
#define ESTRIDE 68
__global__ void __launch_bounds__(512) edge_score_k(const int* __restrict__ ei,
                                                    const float* __restrict__ PA,
                                                    const float* __restrict__ PB,
                                                    const float* __restrict__ Wm2,
                                                    const float* __restrict__ bm2,
                                                    float* __restrict__ out) {
    extern __shared__ float sm[];
    float* pa_s = sm;                     // 256*ESTRIDE
    float* pb_s = sm + 256 * ESTRIDE;     // 256*ESTRIDE
    __shared__ float wm2s[256];
    int g = blockIdx.x, tid = threadIdx.x;
    if (tid < 256) wm2s[tid] = Wm2[tid];
    int base = g * EPG;

    int r[8], c[8];
    float acc[8];
#pragma unroll
    for (int i = 0; i < 8; i++) {
        int j = tid + i * 512;
        r[i] = ei[base + j] - g * NPG;
        c[i] = ei[En + base + j] - g * NPG;
        acc[i] = 0.f;
    }

    for (int p = 0; p < 4; p++) {
        __syncthreads();
        for (int t = tid; t < 4096; t += 512) {
            int nd = t >> 4, kk = (t & 15) * 4;
            *(float4*)&pa_s[nd * ESTRIDE + kk] = *(const float4*)&PA[(g * NPG + nd) * 256 + p * 64 + kk];
            *(float4*)&pb_s[nd * ESTRIDE + kk] = *(const float4*)&PB[(g * NPG + nd) * 256 + p * 64 + kk];
        }
        __syncthreads();
#pragma unroll 4
        for (int kk = 0; kk < 64; kk += 4) {
            float4 w4 = *(const float4*)&wm2s[p * 64 + kk];
#pragma unroll
            for (int i = 0; i < 8; i++) {
                float4 va = *(const float4*)&pa_s[r[i] * ESTRIDE + kk];
                float4 vb = *(const float4*)&pb_s[c[i] * ESTRIDE + kk];
                acc[i] += w4.x * fmaxf(va.x + vb.x, 0.f)
                        + w4.y * fmaxf(va.y + vb.y, 0.f)
                        + w4.z * fmaxf(va.z + vb.z, 0.f)
                        + w4.w * fmaxf(va.w + vb.w, 0.f);
            }
        }
    }
    float bb = bm2[0];
#pragma unroll
    for (int i = 0; i < 8; i++) out[base + tid + i * 512] = acc[i] + bb;
}

// ---------------- per-group stable bitonic argsort (desc score, ties asc idx) ----------------
__global__ void __launch_bounds__(1024) sort_k(const int* __restrict__ ei,
                                               float* __restrict__ out) {
    __shared__ unsigned long long keys[EPG];
    int g = blockIdx.x, tid = threadIdx.x;
    int base = g * EPG;
    for (int j = tid; j < EPG; j += 1024) {
        float s = out[base + j];
        unsigned int b = __float_as_uint(s);
        unsigned int enc = (b & 0x80000000u) ? ~b : (b | 0x80000000u);
        keys[j] = (((unsigned long long)(~enc)) << 32) | (unsigned int)j;
    }
    __syncthreads();
    for (int size = 2; size <= EPG; size <<= 1) {
        for (int stride = size >> 1; stride > 0; stride >>= 1) {
#pragma unroll 2
            for (int t = tid; t < EPG / 2; t += 1024) {
                int lo = ((t & ~(stride - 1)) << 1) | (t & (stride - 1));
                int hi = lo + stride;
                bool asc = ((lo & size) == 0);
                unsigned long long a = keys[lo], b = keys[hi];
                bool sw = asc ? (a > b) : (a < b);
                if (sw) { keys[lo] = b; keys[hi] = a; }
            }
            __syncthreads();
        }
    }
    for (int i2 = tid; i2 < EPG; i2 += 1024) {
        unsigned long long kv = keys[i2];
        int j = (int)(kv & 0xffffffffull);
        unsigned int enc = ~(unsigned int)(kv >> 32);
        unsigned int sb = (enc & 0x80000000u) ? (enc & 0x7fffffffu) : ~enc;
        float s = __uint_as_float(sb);
        int e = base + j;
        int rs = ei[e];
        int rd = ei[En + e];
        if (i2 < Kk) {
            int o = g * Kk + i2;
            out[OFF_CW + o] = s;
            g_keepnodes[o] = rs;
            g_keepnodes[GKn + o] = rd;
            g_presC[rs] = 1;
            g_presC[rd] = 1;
        } else {
            int o = g * Kk + (i2 - Kk);
            out[OFF_DW + o] = -s;
            g_dropnodes[o] = rs;
            g_dropnodes[GKn + o] = rd;
            g_presD[rs] = 1;
            g_presD[rd] = 1;
        }
    }
}

// ---------------- merged scans (y=0: causal, y=1: conf) ----------------
__global__ void __launch_bounds__(1024) scan1_k() {
    __shared__ int ws_[32];
    const int* pres = blockIdx.y ? g_presD : g_presC;
    int* nid = blockIdx.y ? g_nidD : g_nidC;
    int* bsum = blockIdx.y ? g_bsD : g_bsC;
    int i = blockIdx.x * 1024 + threadIdx.x;
    int x = pres[i];
    int v = warp_incl_scan(x);
    int w = threadIdx.x >> 5, lane = threadIdx.x & 31;
    if (lane == 31) ws_[w] = v;
    __syncthreads();
    if (w == 0) { int t = ws_[lane]; t = warp_incl_scan(t); ws_[lane] = t; }
    __syncthreads();
    if (w > 0) v += ws_[w - 1];
    nid[i] = v;
    if (threadIdx.x == 1023) bsum[blockIdx.x] = v;
}

__global__ void scan2_k() {
    int* bsum = (threadIdx.x >= 32) ? g_bsD : g_bsC;
    int idx = threadIdx.x & 31;
    int x = bsum[idx];
    int v = warp_incl_scan(x);
    bsum[idx] = v - x;
}

__global__ void __launch_bounds__(1024) scan3_k(float* __restrict__ out) {
    const int* pres = blockIdx.y ? g_presD : g_presC;
    int* nid = blockIdx.y ? g_nidD : g_nidC;
    const int* bsum = blockIdx.y ? g_bsD : g_bsC;
    float* maskOut = out + (blockIdx.y ? OFF_FMASK : OFF_CMASK);
    int i = blockIdx.x * 1024 + threadIdx.x;
    nid[i] = nid[i] + bsum[blockIdx.x] - 1;
    maskOut[i] = (float)pres[i];
}

// ---------------- final relabeled-edge gather ----------------
__global__ void gather_k(float* __restrict__ out) {
    int i = blockIdx.x * blockDim.x + threadIdx.x;
    if (i >= 2 * GKn) return;
    out[OFF_CEI + i] = (float)g_nidC[g_keepnodes[i]];
    out[OFF_FEI + i] = (float)g_nidD[g_dropnodes[i]];
}

// ---------------- host launch ----------------
extern "C" void kernel_launch(void* const* d_in, const int* in_sizes, int n_in,
                              void* d_out, int out_size) {
    const float* x   = (const float*)d_in[0];
    const float* ea  = (const float*)d_in[1];
    const float* W11 = (const float*)d_in[2];
    const float* b11 = (const float*)d_in[3];
    const float* W12 = (const float*)d_in[4];
    const float* W13 = (const float*)d_in[5];
    const float* b13 = (const float*)d_in[6];
    const float* W21 = (const float*)d_in[7];
    const float* b21 = (const float*)d_in[8];
    const float* W22 = (const float*)d_in[9];
    const float* W23 = (const float*)d_in[10];
    const float* b23 = (const float*)d_in[11];
    const float* Wm1 = (const float*)d_in[12];
    const float* bm1 = (const float*)d_in[13];
    const float* Wm2 = (const float*)d_in[14];
    const float* bm2 = (const float*)d_in[15];
    const int*   ei  = (const int*)d_in[16];   // int32 (JAX x64 disabled)
    float* out = (float*)d_out;

    float *A, *B, *C, *H1, *H2, *PA, *PB;
    cudaGetSymbolAddress((void**)&A, g_A);
    cudaGetSymbolAddress((void**)&B, g_B);
    cudaGetSymbolAddress((void**)&C, g_C);
    cudaGetSymbolAddress((void**)&H1, g_H1);
    cudaGetSymbolAddress((void**)&H2, g_H2);
    cudaGetSymbolAddress((void**)&PA, g_PA);
    cudaGetSymbolAddress((void**)&PB, g_PB);

    const int esSmem = 2 * 256 * ESTRIDE * sizeof(float); // 136 KB
    cudaFuncSetAttribute(edge_score_k, cudaFuncAttributeMaxDynamicSharedMemorySize, esSmem);

    csr_build_k<<<Gn, 256>>>(ei, ea);

    // ---- leconv 1 ----
    gemmL_k<<<dim3(Nn / 64, 3), 256>>>(x, W11, b11, W12, W13, b13);
    aggc_k<<<Nn / 8, 256>>>(A, B, C, H1, 1);

    // ---- leconv 2 ----
    gemmL_k<<<dim3(Nn / 64, 3), 256>>>(H1, W21, b21, W22, W23, b23);
    aggc_k<<<Nn / 8, 256>>>(A, B, C, H2, 0);

    // ---- MLP node projections (PA | PB) ----
    gemmM_k<<<dim3(Nn / 64, 8), 256>>>(H2, Wm1, bm1);

    // ---- per-edge scores ----
    edge_score_k<<<Gn, 512, esSmem>>>(ei, PA, PB, Wm2, bm2, out);

    // ---- per-group sort + keep/drop split ----
    sort_k<<<Gn, 1024>>>(ei, out);

    // ---- relabel scans (both graphs, merged) ----
    scan1_k<<<dim3(32, 2), 1024>>>();
    scan2_k<<<1, 64>>>();
    scan3_k<<<dim3(32, 2), 1024>>>(out);

    // ---- relabeled edge index gather ----
    gather_k<<<(2 * GKn) / 256, 256>>>(out);
}

// round 8
// speedup vs baseline: 1.7009x; 1.0094x over previous
#include <cuda_runtime.h>

// ---------------- problem constants ----------------
#define Gn   128
#define NPG  256
#define EPG  4096
#define Nn   (Gn*NPG)          // 32768 nodes
#define En   (Gn*EPG)          // 524288 edges
#define Kk   2048              // kept edges per group
#define GKn  (Gn*Kk)           // 262144

// output layout (all f32, flattened tuple in reference order)
#define OFF_SCORE 0
#define OFF_CW    (En)
#define OFF_DW    (En + GKn)
#define OFF_CEI   (En + 2*GKn)
#define OFF_FEI   (En + 4*GKn)
#define OFF_CMASK (En + 6*GKn)
#define OFF_FMASK (En + 6*GKn + Nn)

// ---------------- device scratch ----------------
__device__ float g_A[Nn*64];
__device__ float g_B[Nn*64];
__device__ float g_C[Nn*64];
__device__ float g_H1[Nn*64];
__device__ float g_H2[Nn*64];
__device__ float g_PA[Nn*256];
__device__ float g_PB[Nn*256];
__device__ int   g_rows[En];      // LOCAL src node id (0..255)
__device__ float g_ews[En];
__device__ int   g_start[Nn];
__device__ int   g_keepnodes[2*GKn];
__device__ int   g_dropnodes[2*GKn];
__device__ int   g_presC[Nn];
__device__ int   g_presD[Nn];
__device__ int   g_nidC[Nn];
__device__ int   g_nidD[Nn];
__device__ int   g_bsC[32];
__device__ int   g_bsD[32];

// ---------------- helpers ----------------
__device__ __forceinline__ int warp_incl_scan(int v) {
    int lane = threadIdx.x & 31;
#pragma unroll
    for (int o = 1; o < 32; o <<= 1) {
        int t = __shfl_up_sync(0xffffffffu, v, o);
        if (lane >= o) v += t;
    }
    return v;
}

__device__ __forceinline__ void fma2(unsigned long long& d, unsigned long long a, unsigned long long b) {
    asm("fma.rn.f32x2 %0, %1, %2, %0;" : "+l"(d) : "l"(a), "l"(b));
}
__device__ __forceinline__ unsigned long long add2(unsigned long long a, unsigned long long b) {
    unsigned long long d;
    asm("add.rn.f32x2 %0, %1, %2;" : "=l"(d) : "l"(a), "l"(b));
    return d;
}
// packed relu: unpack (free reg-pair), 2x FMNMX, repack (reg-pair mov)
__device__ __forceinline__ unsigned long long relu2(unsigned long long a) {
    float lo, hi;
    asm("mov.b64 {%0,%1}, %2;" : "=f"(lo), "=f"(hi) : "l"(a));
    lo = fmaxf(lo, 0.f);
    hi = fmaxf(hi, 0.f);
    unsigned long long d;
    asm("mov.b64 %0, {%1,%2};" : "=l"(d) : "f"(lo), "f"(hi));
    return d;
}
__device__ __forceinline__ float2 up2(unsigned long long v) {
    float2 f;
    asm("mov.b64 {%0,%1}, %2;" : "=f"(f.x), "=f"(f.y) : "l"(v));
    return f;
}
__device__ __forceinline__ float red2(unsigned long long v) {
    float2 f = up2(v);
    return f.x + f.y;
}

// ---------------- deterministic per-group CSR (counting sort by dst) + zero pres ----------------
__global__ void __launch_bounds__(256) csr_build_k(const int* __restrict__ ei,
                                                   const float* __restrict__ ea) {
    __shared__ int hist[8][256];
    __shared__ int wsums[8];
    int g = blockIdx.x, tid = threadIdx.x;
    int w = tid >> 5, lane = tid & 31;
    int base = g * EPG;

    g_presC[g * NPG + tid] = 0;
    g_presD[g * NPG + tid] = 0;

#pragma unroll
    for (int i = 0; i < 8; i++) hist[i][tid] = 0;
    __syncthreads();

    for (int rnd = 0; rnd < 16; rnd++) {
        int j = w * 512 + rnd * 32 + lane;
        int c = ei[En + base + j] - g * NPG;
        atomicAdd(&hist[w][c], 1);
    }
    __syncthreads();

    int s = 0;
#pragma unroll
    for (int i = 0; i < 8; i++) { int h = hist[i][tid]; hist[i][tid] = s; s += h; }
    int incl = warp_incl_scan(s);
    if (lane == 31) wsums[w] = incl;
    __syncthreads();
    if (tid == 0) { int a = 0; for (int i = 0; i < 8; i++) { int t = wsums[i]; wsums[i] = a; a += t; } }
    __syncthreads();
    int excl_c = incl - s + wsums[w];
    g_start[g * NPG + tid] = base + excl_c;
#pragma unroll
    for (int i = 0; i < 8; i++) hist[i][tid] += excl_c;
    __syncthreads();

    for (int rnd = 0; rnd < 16; rnd++) {
        int j = w * 512 + rnd * 32 + lane;
        int r = ei[base + j] - g * NPG;          // LOCAL id
        int c = ei[En + base + j] - g * NPG;
        float wv = ea[base + j];
        unsigned mask = __match_any_sync(0xffffffffu, c);
        int rank = __popc(mask & ((1u << lane) - 1u));
        int cur = hist[w][c];
        __syncwarp();
        if (lane == (__ffs(mask) - 1)) hist[w][c] = cur + __popc(mask);
        g_rows[base + cur + rank] = r;
        g_ews[base + cur + rank]  = wv;
        __syncwarp();
    }
}

// ================= stride-68 linear f32x2 GEMM core =================
// Tiles [64 rows x 64 k], k-major, row stride 68 floats (272B = 16B-aligned).
// Per 8-lane phase: disjoint banks -> conflict-free LDS.128 with pure [base+imm] addressing.
// 256 threads: tf = tid & 15 owns f rows {tf+16j}, tv = tid >> 4 owns v rows {tv+16i}.
#define TSTR 68

__device__ __forceinline__ void gemm_core(const float* __restrict__ Xs,
                                          const float* __restrict__ Ws,
                                          int tf, int tv,
                                          unsigned long long acc[4][4]) {
    const float* xb0 = &Xs[tv * TSTR];
    const float* wb0 = &Ws[tf * TSTR];
#pragma unroll 4
    for (int gk = 0; gk < 16; gk++) {
        ulonglong2 xq[4], wq[4];
#pragma unroll
        for (int i = 0; i < 4; i++)
            xq[i] = *(const ulonglong2*)(xb0 + i * (16 * TSTR) + gk * 4);
#pragma unroll
        for (int j = 0; j < 4; j++)
            wq[j] = *(const ulonglong2*)(wb0 + j * (16 * TSTR) + gk * 4);
#pragma unroll
        for (int i = 0; i < 4; i++)
#pragma unroll
            for (int j = 0; j < 4; j++) {
                fma2(acc[i][j], xq[i].x, wq[j].x);
                fma2(acc[i][j], xq[i].y, wq[j].y);
            }
    }
}

// load a 64x64 tile (row stride lds in gmem) into stride-68 smem
__device__ __forceinline__ void load_tile(float* __restrict__ dst,
                                          const float* __restrict__ src, int lds,
                                          int tid) {
#pragma unroll
    for (int t = tid; t < 1024; t += 256) {
        int row = t >> 4, g = t & 15;
        *(float4*)&dst[row * TSTR + g * 4] = *(const float4*)&src[row * lds + g * 4];
    }
}

// leconv layer: grid (Nn/64, 3): y=0 -> A=X@W1'+b1, y=1 -> B=X@W2', y=2 -> C=X@W3'+b3
__global__ void __launch_bounds__(256) gemmL_k(const float* __restrict__ X,
                                               const float* __restrict__ W1,
                                               const float* __restrict__ b1,
                                               const float* __restrict__ W2,
                                               const float* __restrict__ W3,
                                               const float* __restrict__ b3) {
    __shared__ __align__(16) float Xs[64 * TSTR];
    __shared__ __align__(16) float Ws[64 * TSTR];
    int tid = threadIdx.x;
    int vtile = blockIdx.x * 64;
    int m = blockIdx.y;
    const float* W = (m == 0) ? W1 : ((m == 1) ? W2 : W3);
    const float* bias = (m == 0) ? b1 : ((m == 2) ? b3 : nullptr);
    float* Y = (m == 0) ? g_A : ((m == 1) ? g_B : g_C);

    load_tile(Xs, X + vtile * 64, 64, tid);
    load_tile(Ws, W, 64, tid);
    __syncthreads();

    int tf = tid & 15, tv = tid >> 4;
    unsigned long long acc[4][4];
#pragma unroll
    for (int i = 0; i < 4; i++)
#pragma unroll
        for (int j = 0; j < 4; j++) acc[i][j] = 0ull;

    gemm_core(Xs, Ws, tf, tv, acc);

    float bj[4] = {0.f, 0.f, 0.f, 0.f};
    if (bias) {
#pragma unroll
        for (int j = 0; j < 4; j++) bj[j] = bias[tf + 16 * j];
    }
#pragma unroll
    for (int i = 0; i < 4; i++)
#pragma unroll
        for (int j = 0; j < 4; j++)
            Y[(vtile + tv + 16 * i) * 64 + tf + 16 * j] = red2(acc[i][j]) + bj[j];
}

// MLP projection: grid (Nn/64, 8): y<4 -> PA tile y, y>=4 -> PB tile y-4. Wm1 rows stride 128.
__global__ void __launch_bounds__(256) gemmM_k(const float* __restrict__ X,
                                               const float* __restrict__ Wm1,
                                               const float* __restrict__ bm1) {
    __shared__ __align__(16) float Xs[64 * TSTR];
    __shared__ __align__(16) float Ws[64 * TSTR];
    int tid = threadIdx.x;
    int vtile = blockIdx.x * 64;
    int y = blockIdx.y;
    int isB = (y >= 4);
    int ftile = (y & 3) * 64;
    int koff = isB ? 64 : 0;
    float* Y = isB ? g_PB : g_PA;

    load_tile(Xs, X + vtile * 64, 64, tid);
    load_tile(Ws, Wm1 + ftile * 128 + koff, 128, tid);
    __syncthreads();

    int tf = tid & 15, tv = tid >> 4;
    unsigned long long acc[4][4];
#pragma unroll
    for (int i = 0; i < 4; i++)
#pragma unroll
        for (int j = 0; j < 4; j++) acc[i][j] = 0ull;

    gemm_core(Xs, Ws, tf, tv, acc);

    float bj[4] = {0.f, 0.f, 0.f, 0.f};
    if (!isB) {
#pragma unroll
        for (int j = 0; j < 4; j++) bj[j] = bm1[ftile + tf + 16 * j];
    }
#pragma unroll
    for (int i = 0; i < 4; i++)
#pragma unroll
        for (int j = 0; j < 4; j++)
            Y[(vtile + tv + 16 * i) * 256 + ftile + tf + 16 * j] = red2(acc[i][j]) + bj[j];
}

// ---------------- gather-aggregate + combine -------------
__global__ void aggc_k(const float* __restrict__ A, const float* __restrict__ B,
                       const float* __restrict__ C, float* __restrict__ H, int doRelu) {
    int warp = blockIdx.x * (blockDim.x >> 5) + (threadIdx.x >> 5);
    int lane = threadIdx.x & 31;
    if (warp >= Nn) return;
    int v = warp;
    int s = g_start[v];
    int g = v >> 8;
    int e = ((v & 255) == 255) ? (g * EPG + EPG) : g_start[v + 1];
    int abase = g * NPG * 64;
    float2 acc = make_float2(0.f, 0.f);
    float ws = 0.f;
    for (int i = s; i < e; i++) {
        int r = g_rows[i];
        float w = g_ews[i];
        float2 a = *(const float2*)&A[abase + r * 64 + lane * 2];
        acc.x += w * a.x;
        acc.y += w * a.y;
        ws += w;
    }
    float2 bv = *(const float2*)&B[v * 64 + lane * 2];
    float2 cv = *(const float2*)&C[v * 64 + lane * 2];
    float hx = acc.x - ws * bv.x + cv.x;
    float hy = acc.y - ws * bv.y + cv.y;
    if (doRelu) { hx = fmaxf(hx, 0.f); hy = fmaxf(hy, 0.f); }
    *(float2*)&H[v * 64 + lane * 2] = make_float2(hx, hy);
}

// ---------------- per-edge score: smem-staged packed-f32x2 relu-dot ----------------
#define ESTRIDE 68
__global__ void __launch_bounds__(512) edge_score_k(const int* __restrict__ ei,
                                                    const float* __restrict__ PA,
                                                    const float* __restrict__ PB,
                                                    const float* __restrict__ Wm2,
                                                    const float* __restrict__ bm2,
                                                    float* __restrict__ out) {
    extern __shared__ float sm[];
    float* pa_s = sm;                     // 256*ESTRIDE
    float* pb_s = sm + 256 * ESTRIDE;     // 256*ESTRIDE
    __shared__ __align__(16) float wm2s[256];
    int g = blockIdx.x, tid = threadIdx.x;
    if (tid < 256) wm2s[tid] = Wm2[tid];
    int base = g * EPG;

    int r[8], c[8];
    unsigned long long acc2[8];
#pragma unroll
    for (int i = 0; i < 8; i++) {
        int j = tid + i * 512;
        r[i] = ei[base + j] - g * NPG;
        c[i] = ei[En + base + j] - g * NPG;
        acc2[i] = 0ull;
    }

    for (int p = 0; p < 4; p++) {
        __syncthreads();
        for (int t = tid; t < 4096; t += 512) {
            int nd = t >> 4, kk = (t & 15) * 4;
            *(float4*)&pa_s[nd * ESTRIDE + kk] = *(const float4*)&PA[(g * NPG + nd) * 256 + p * 64 + kk];
            *(float4*)&pb_s[nd * ESTRIDE + kk] = *(const float4*)&PB[(g * NPG + nd) * 256 + p * 64 + kk];
        }
        __syncthreads();
#pragma unroll 4
        for (int kk = 0; kk < 64; kk += 4) {
            ulonglong2 w2 = *(const ulonglong2*)&wm2s[p * 64 + kk];
#pragma unroll
            for (int i = 0; i < 8; i++) {
                ulonglong2 va = *(const ulonglong2*)&pa_s[r[i] * ESTRIDE + kk];
                ulonglong2 vb = *(const ulonglong2*)&pb_s[c[i] * ESTRIDE + kk];
                unsigned long long s0 = relu2(add2(va.x, vb.x));
                unsigned long long s1 = relu2(add2(va.y, vb.y));
                fma2(acc2[i], s0, w2.x);
                fma2(acc2[i], s1, w2.y);
            }
        }
    }
    float bb = bm2[0];
#pragma unroll
    for (int i = 0; i < 8; i++) out[base + tid + i * 512] = red2(acc2[i]) + bb;
}

// ---------------- per-group stable bitonic argsort (desc score, ties asc idx) ----------------
__global__ void __launch_bounds__(1024) sort_k(const int* __restrict__ ei,
                                               float* __restrict__ out) {
    __shared__ unsigned long long keys[EPG];
    int g = blockIdx.x, tid = threadIdx.x;
    int base = g * EPG;
    for (int j = tid; j < EPG; j += 1024) {
        float s = out[base + j];
        unsigned int b = __float_as_uint(s);
        unsigned int enc = (b & 0x80000000u) ? ~b : (b | 0x80000000u);
        keys[j] = (((unsigned long long)(~enc)) << 32) | (unsigned int)j;
    }
    __syncthreads();
    for (int size = 2; size <= EPG; size <<= 1) {
        for (int stride = size >> 1; stride > 0; stride >>= 1) {
#pragma unroll 2
            for (int t = tid; t < EPG / 2; t += 1024) {
                int lo = ((t & ~(stride - 1)) << 1) | (t & (stride - 1));
                int hi = lo + stride;
                bool asc = ((lo & size) == 0);
                unsigned long long a = keys[lo], b = keys[hi];
                bool sw = asc ? (a > b) : (a < b);
                if (sw) { keys[lo] = b; keys[hi] = a; }
            }
            __syncthreads();
        }
    }
    for (int i2 = tid; i2 < EPG; i2 += 1024) {
        unsigned long long kv = keys[i2];
        int j = (int)(kv & 0xffffffffull);
        unsigned int enc = ~(unsigned int)(kv >> 32);
        unsigned int sb = (enc & 0x80000000u) ? (enc & 0x7fffffffu) : ~enc;
        float s = __uint_as_float(sb);
        int e = base + j;
        int rs = ei[e];
        int rd = ei[En + e];
        if (i2 < Kk) {
            int o = g * Kk + i2;
            out[OFF_CW + o] = s;
            g_keepnodes[o] = rs;
            g_keepnodes[GKn + o] = rd;
            g_presC[rs] = 1;
            g_presC[rd] = 1;
        } else {
            int o = g * Kk + (i2 - Kk);
            out[OFF_DW + o] = -s;
            g_dropnodes[o] = rs;
            g_dropnodes[GKn + o] = rd;
            g_presD[rs] = 1;
            g_presD[rd] = 1;
        }
    }
}

// ---------------- merged scans (y=0: causal, y=1: conf) ----------------
__global__ void __launch_bounds__(1024) scan1_k() {
    __shared__ int ws_[32];
    const int* pres = blockIdx.y ? g_presD : g_presC;
    int* nid = blockIdx.y ? g_nidD : g_nidC;
    int* bsum = blockIdx.y ? g_bsD : g_bsC;
    int i = blockIdx.x * 1024 + threadIdx.x;
    int x = pres[i];
    int v = warp_incl_scan(x);
    int w = threadIdx.x >> 5, lane = threadIdx.x & 31;
    if (lane == 31) ws_[w] = v;
    __syncthreads();
    if (w == 0) { int t = ws_[lane]; t = warp_incl_scan(t); ws_[lane] = t; }
    __syncthreads();
    if (w > 0) v += ws_[w - 1];
    nid[i] = v;
    if (threadIdx.x == 1023) bsum[blockIdx.x] = v;
}

__global__ void scan2_k() {
    int* bsum = (threadIdx.x >= 32) ? g_bsD : g_bsC;
    int idx = threadIdx.x & 31;
    int x = bsum[idx];
    int v = warp_incl_scan(x);
    bsum[idx] = v - x;
}

__global__ void __launch_bounds__(1024) scan3_k(float* __restrict__ out) {
    const int* pres = blockIdx.y ? g_presD : g_presC;
    int* nid = blockIdx.y ? g_nidD : g_nidC;
    const int* bsum = blockIdx.y ? g_bsD : g_bsC;
    float* maskOut = out + (blockIdx.y ? OFF_FMASK : OFF_CMASK);
    int i = blockIdx.x * 1024 + threadIdx.x;
    nid[i] = nid[i] + bsum[blockIdx.x] - 1;
    maskOut[i] = (float)pres[i];
}

// ---------------- final relabeled-edge gather ----------------
__global__ void gather_k(float* __restrict__ out) {
    int i = blockIdx.x * blockDim.x + threadIdx.x;
    if (i >= 2 * GKn) return;
    out[OFF_CEI + i] = (float)g_nidC[g_keepnodes[i]];
    out[OFF_FEI + i] = (float)g_nidD[g_dropnodes[i]];
}

// ---------------- host launch ----------------
extern "C" void kernel_launch(void* const* d_in, const int* in_sizes, int n_in,
                              void* d_out, int out_size) {
    const float* x   = (const float*)d_in[0];
    const float* ea  = (const float*)d_in[1];
    const float* W11 = (const float*)d_in[2];
    const float* b11 = (const float*)d_in[3];
    const float* W12 = (const float*)d_in[4];
    const float* W13 = (const float*)d_in[5];
    const float* b13 = (const float*)d_in[6];
    const float* W21 = (const float*)d_in[7];
    const float* b21 = (const float*)d_in[8];
    const float* W22 = (const float*)d_in[9];
    const float* W23 = (const float*)d_in[10];
    const float* b23 = (const float*)d_in[11];
    const float* Wm1 = (const float*)d_in[12];
    const float* bm1 = (const float*)d_in[13];
    const float* Wm2 = (const float*)d_in[14];
    const float* bm2 = (const float*)d_in[15];
    const int*   ei  = (const int*)d_in[16];   // int32 (JAX x64 disabled)
    float* out = (float*)d_out;

    float *A, *B, *C, *H1, *H2, *PA, *PB;
    cudaGetSymbolAddress((void**)&A, g_A);
    cudaGetSymbolAddress((void**)&B, g_B);
    cudaGetSymbolAddress((void**)&C, g_C);
    cudaGetSymbolAddress((void**)&H1, g_H1);
    cudaGetSymbolAddress((void**)&H2, g_H2);
    cudaGetSymbolAddress((void**)&PA, g_PA);
    cudaGetSymbolAddress((void**)&PB, g_PB);

    const int esSmem = 2 * 256 * ESTRIDE * sizeof(float); // 136 KB
    cudaFuncSetAttribute(edge_score_k, cudaFuncAttributeMaxDynamicSharedMemorySize, esSmem);

    csr_build_k<<<Gn, 256>>>(ei, ea);

    // ---- leconv 1 ----
    gemmL_k<<<dim3(Nn / 64, 3), 256>>>(x, W11, b11, W12, W13, b13);
    aggc_k<<<Nn / 8, 256>>>(A, B, C, H1, 1);

    // ---- leconv 2 ----
    gemmL_k<<<dim3(Nn / 64, 3), 256>>>(H1, W21, b21, W22, W23, b23);
    aggc_k<<<Nn / 8, 256>>>(A, B, C, H2, 0);

    // ---- MLP node projections (PA | PB) ----
    gemmM_k<<<dim3(Nn / 64, 8), 256>>>(H2, Wm1, bm1);

    // ---- per-edge scores ----
    edge_score_k<<<Gn, 512, esSmem>>>(ei, PA, PB, Wm2, bm2, out);

    // ---- per-group sort + keep/drop split ----
    sort_k<<<Gn, 1024>>>(ei, out);

    // ---- relabel scans (both graphs, merged) ----
    scan1_k<<<dim3(32, 2), 1024>>>();
    scan2_k<<<1, 64>>>();
    scan3_k<<<dim3(32, 2), 1024>>>(out);

    // ---- relabeled edge index gather ----
    gather_k<<<(2 * GKn) / 256, 256>>>(out);
}